// round 1
// baseline (speedup 1.0000x reference)
#include <cuda_runtime.h>
#include <math.h>

// Problem constants (fixed shapes)
#define B_   16
#define C_   256
#define H_   32
#define W_   32
#define N_   1024           // H*W
#define NH_  4
#define KD_  32             // head key dim
#define HD_  64             // head value dim
#define CQKV 512            // C + 2*kd*NH
#define HID  512            // 2*C / 2 ... hid = 2*C = 512
#define C2   1024           // 2*hid
#define P_   8

// ---------------- static scratch (no allocations allowed) ----------------
__device__ float g_qkv   [(size_t)B_*CQKV*N_];        // 32MB
__device__ float g_attn  [(size_t)B_*NH_*N_*N_];      // 256MB
__device__ float g_attout[(size_t)B_*C_*N_];          // 16MB (att out + pe)
__device__ float g_xnew  [(size_t)B_*C_*N_];          // 16MB
__device__ float g_pin   [(size_t)B_*C2*N_];          // 64MB
__device__ float g_dw    [(size_t)B_*C2*N_];          // 64MB
__device__ float g_hid   [(size_t)B_*HID*N_];         // 32MB
__device__ float g_yout  [(size_t)B_*C_*N_];          // 16MB
__device__ float g_g     [C_*64];                     // circ-conv kernels

// ---------------- generic conv1x1 GEMM: out[b,o,n] = sum_c W[o,c] in[b,c,n]
// optional per-o affine (scale,bias) and residual add.
// BM=BN=64, BK=16, 256 threads, 4x4 micro-tile
__global__ void gemm1x1_kernel(const float* __restrict__ in,
                               const float* __restrict__ w,
                               const float* __restrict__ scale,
                               const float* __restrict__ bias,
                               const float* __restrict__ residual,
                               float* __restrict__ out,
                               int Cin, int Cout, int N)
{
    __shared__ float Ws[16][65];   // [k][o]
    __shared__ float Is[16][64];   // [k][n]
    const int b  = blockIdx.z;
    const int o0 = blockIdx.y * 64;
    const int n0 = blockIdx.x * 64;
    const int tid = threadIdx.x;
    const int tx = tid & 15;
    const int ty = tid >> 4;

    const float* inb = in + (size_t)b * Cin * N;
    float acc[4][4];
#pragma unroll
    for (int i = 0; i < 4; i++)
#pragma unroll
        for (int j = 0; j < 4; j++) acc[i][j] = 0.f;

    for (int k0 = 0; k0 < Cin; k0 += 16) {
        // load W tile (64 o x 16 c), coalesced along c
#pragma unroll
        for (int l = tid; l < 1024; l += 256) {
            int cc = l & 15, oo = l >> 4;
            Ws[cc][oo] = w[(size_t)(o0 + oo) * Cin + k0 + cc];
        }
        // load input tile (16 c x 64 n), coalesced along n
#pragma unroll
        for (int l = tid; l < 1024; l += 256) {
            int nn = l & 63, kk = l >> 6;
            Is[kk][nn] = inb[(size_t)(k0 + kk) * N + n0 + nn];
        }
        __syncthreads();
#pragma unroll
        for (int k = 0; k < 16; k++) {
            float ra[4], rb[4];
#pragma unroll
            for (int i = 0; i < 4; i++) ra[i] = Ws[k][ty * 4 + i];
#pragma unroll
            for (int j = 0; j < 4; j++) rb[j] = Is[k][tx * 4 + j];
#pragma unroll
            for (int i = 0; i < 4; i++)
#pragma unroll
                for (int j = 0; j < 4; j++) acc[i][j] += ra[i] * rb[j];
        }
        __syncthreads();
    }

#pragma unroll
    for (int i = 0; i < 4; i++) {
        int o = o0 + ty * 4 + i;
        float sc = scale ? scale[o] : 1.f;
        float bi = scale ? bias[o]  : 0.f;
#pragma unroll
        for (int j = 0; j < 4; j++) {
            int n = n0 + tx * 4 + j;
            float v = acc[i][j] * sc + bi;
            size_t oi = ((size_t)b * Cout + o) * N + n;
            if (residual) v += residual[oi];
            out[oi] = v;
        }
    }
}

// ---------------- attention S = Q^T K * scale --------------------------
__global__ void attn_qk_kernel(const float* __restrict__ qkv,
                               float* __restrict__ attn, float scale)
{
    __shared__ float Qs[16][64];
    __shared__ float Ks[16][64];
    const int bh = blockIdx.z;
    const int b = bh / NH_, h = bh % NH_;
    const int n0 = blockIdx.y * 64;
    const int m0 = blockIdx.x * 64;
    const int tid = threadIdx.x;
    const int tx = tid & 15, ty = tid >> 4;

    const float* qb = qkv + ((size_t)b * CQKV + h * 128) * N_;
    const float* kb = qb + (size_t)KD_ * N_;

    float acc[4][4];
#pragma unroll
    for (int i = 0; i < 4; i++)
#pragma unroll
        for (int j = 0; j < 4; j++) acc[i][j] = 0.f;

    for (int d0 = 0; d0 < KD_; d0 += 16) {
#pragma unroll
        for (int l = tid; l < 1024; l += 256) {
            int nn = l & 63, dd = l >> 6;
            Qs[dd][nn] = qb[(size_t)(d0 + dd) * N_ + n0 + nn];
            Ks[dd][nn] = kb[(size_t)(d0 + dd) * N_ + m0 + nn];
        }
        __syncthreads();
#pragma unroll
        for (int k = 0; k < 16; k++) {
            float ra[4], rb[4];
#pragma unroll
            for (int i = 0; i < 4; i++) ra[i] = Qs[k][ty * 4 + i];
#pragma unroll
            for (int j = 0; j < 4; j++) rb[j] = Ks[k][tx * 4 + j];
#pragma unroll
            for (int i = 0; i < 4; i++)
#pragma unroll
                for (int j = 0; j < 4; j++) acc[i][j] += ra[i] * rb[j];
        }
        __syncthreads();
    }
#pragma unroll
    for (int i = 0; i < 4; i++) {
        int n = n0 + ty * 4 + i;
#pragma unroll
        for (int j = 0; j < 4; j++) {
            int m = m0 + tx * 4 + j;
            attn[((size_t)bh * N_ + n) * N_ + m] = acc[i][j] * scale;
        }
    }
}

// ---------------- row softmax ------------------------------------------
__global__ void softmax_kernel(float* __restrict__ attn)
{
    __shared__ float red[256];
    const size_t row = blockIdx.x;
    float* p = attn + row * N_;
    const int tid = threadIdx.x;

    float m = -1e30f;
    for (int i = tid; i < N_; i += 256) m = fmaxf(m, p[i]);
    red[tid] = m; __syncthreads();
    for (int s = 128; s > 0; s >>= 1) { if (tid < s) red[tid] = fmaxf(red[tid], red[tid + s]); __syncthreads(); }
    m = red[0]; __syncthreads();

    float sum = 0.f;
    for (int i = tid; i < N_; i += 256) { float e = expf(p[i] - m); p[i] = e; sum += e; }
    red[tid] = sum; __syncthreads();
    for (int s = 128; s > 0; s >>= 1) { if (tid < s) red[tid] += red[tid + s]; __syncthreads(); }
    float inv = 1.f / red[0];
    for (int i = tid; i < N_; i += 256) p[i] *= inv;
}

// ---------------- out = V @ attn^T  -------------------------------------
__global__ void attn_pv_kernel(const float* __restrict__ qkv,
                               const float* __restrict__ attn,
                               float* __restrict__ out)
{
    __shared__ float Vs[16][65];
    __shared__ float Ss[16][65];
    const int bh = blockIdx.z;
    const int b = bh / NH_, h = bh % NH_;
    const int n0 = blockIdx.x * 64;
    const int tid = threadIdx.x;
    const int tx = tid & 15, ty = tid >> 4;

    const float* vb = qkv + ((size_t)b * CQKV + h * 128 + 2 * KD_) * N_;
    const float* sb = attn + (size_t)bh * N_ * N_;

    float acc[4][4];
#pragma unroll
    for (int i = 0; i < 4; i++)
#pragma unroll
        for (int j = 0; j < 4; j++) acc[i][j] = 0.f;

    for (int m0 = 0; m0 < N_; m0 += 16) {
#pragma unroll
        for (int l = tid; l < 1024; l += 256) {
            int mm = l & 15, rr = l >> 4;
            Vs[mm][rr] = vb[(size_t)rr * N_ + m0 + mm];         // d = rr
            Ss[mm][rr] = sb[(size_t)(n0 + rr) * N_ + m0 + mm];  // n = rr
        }
        __syncthreads();
#pragma unroll
        for (int k = 0; k < 16; k++) {
            float ra[4], rb[4];
#pragma unroll
            for (int i = 0; i < 4; i++) ra[i] = Vs[k][ty * 4 + i];
#pragma unroll
            for (int j = 0; j < 4; j++) rb[j] = Ss[k][tx * 4 + j];
#pragma unroll
            for (int i = 0; i < 4; i++)
#pragma unroll
                for (int j = 0; j < 4; j++) acc[i][j] += ra[i] * rb[j];
        }
        __syncthreads();
    }
#pragma unroll
    for (int i = 0; i < 4; i++) {
        int d = ty * 4 + i;
#pragma unroll
        for (int j = 0; j < 4; j++) {
            int n = n0 + tx * 4 + j;
            out[((size_t)b * C_ + h * HD_ + d) * N_ + n] = acc[i][j];
        }
    }
}

// ---------------- depthwise 3x3, SAME zero pad ---------------------------
// vmap: map logical channel c to qkv channel (c/64)*128 + 64 + (c%64)
__global__ void dwconv_kernel(const float* __restrict__ in,
                              const float* __restrict__ w,
                              const float* __restrict__ scale,
                              const float* __restrict__ bias,
                              float* __restrict__ out,
                              int C, int CinTotal, int vmap, int accum)
{
    int idx = blockIdx.x * blockDim.x + threadIdx.x;
    int total = B_ * C * H_ * W_;
    if (idx >= total) return;
    int xw = idx & (W_ - 1);
    int yh = (idx / W_) & (H_ - 1);
    int c  = (idx / (W_ * H_)) % C;
    int b  = idx / (W_ * H_ * C);
    int cin = vmap ? ((c >> 6) * 128 + 64 + (c & 63)) : c;
    const float* ip = in + ((size_t)b * CinTotal + cin) * (H_ * W_);
    const float* wp = w + c * 9;
    float s = 0.f;
#pragma unroll
    for (int dy = -1; dy <= 1; dy++) {
        int yy = yh + dy;
        if (yy < 0 || yy >= H_) continue;
#pragma unroll
        for (int dx = -1; dx <= 1; dx++) {
            int xx = xw + dx;
            if (xx < 0 || xx >= W_) continue;
            s += ip[yy * W_ + xx] * wp[(dy + 1) * 3 + (dx + 1)];
        }
    }
    if (scale) s = s * scale[c] + bias[c];
    if (accum) out[idx] += s; else out[idx] = s;
}

// ---------------- GELU(y1) * y2 gate -------------------------------------
__global__ void gate_kernel(const float* __restrict__ dw, float* __restrict__ hid)
{
    int idx = blockIdx.x * blockDim.x + threadIdx.x;
    int total = B_ * HID * N_;
    if (idx >= total) return;
    int n = idx % N_;
    int c = (idx / N_) % HID;
    int b = idx / (N_ * HID);
    float y1 = dw[((size_t)b * C2 + c) * N_ + n];
    float y2 = dw[((size_t)b * C2 + HID + c) * N_ + n];
    float g = 0.5f * y1 * (1.f + erff(y1 * 0.70710678118654752f));
    hid[idx] = g * y2;
}

// ---------------- FFT filter -> 8x8 circular-conv kernel ------------------
__global__ void fft_g_kernel(const float* __restrict__ filt, float* __restrict__ g)
{
    const float ct[8] = {1.f, 0.70710678118654752f, 0.f, -0.70710678118654752f,
                         -1.f, -0.70710678118654752f, 0.f, 0.70710678118654752f};
    int c = blockIdx.x;
    int t = threadIdx.x;           // 64
    int a = t >> 3, bb = t & 7;
    float s = 0.f;
    for (int k1 = 0; k1 < 8; k1++) {
        for (int k2 = 0; k2 < 8; k2++) {
            float F = (k2 <= 4) ? filt[c * 40 + k1 * 5 + k2]
                                : filt[c * 40 + ((8 - k1) & 7) * 5 + (8 - k2)];
            s += F * ct[(k1 * a + k2 * bb) & 7];
        }
    }
    g[c * 64 + t] = s * (1.f / 64.f);
}

// ---------------- per-8x8-block circular conv + final residual ----------
__global__ void fft_apply_kernel(const float* __restrict__ y,
                                 const float* __restrict__ g,
                                 const float* __restrict__ xnew,
                                 float* __restrict__ out)
{
    __shared__ float ys[32 * 32];
    __shared__ float gs[64];
    int bc = blockIdx.x;             // b*C + c
    int c = bc % C_;
    const float* yp = y + (size_t)bc * (H_ * W_);
    int tid = threadIdx.x;
    for (int i = tid; i < 1024; i += 256) ys[i] = yp[i];
    if (tid < 64) gs[tid] = g[c * 64 + tid];
    __syncthreads();
    for (int i = tid; i < 1024; i += 256) {
        int u = i >> 5, v = i & 31;
        int bu = u & ~7, bv = v & ~7;
        int uu = u & 7, vv = v & 7;
        float s = 0.f;
#pragma unroll
        for (int a = 0; a < 8; a++) {
            const float* yr = &ys[(bu + a) * 32 + bv];
            const float* gr = &gs[((uu - a) & 7) * 8];
#pragma unroll
            for (int b2 = 0; b2 < 8; b2++)
                s += gr[(vv - b2) & 7] * yr[b2];
        }
        size_t oi = (size_t)bc * 1024 + i;
        out[oi] = xnew[oi] + s;
    }
}

// =========================================================================
extern "C" void kernel_launch(void* const* d_in, const int* in_sizes, int n_in,
                              void* d_out, int out_size)
{
    const float* x        = (const float*)d_in[0];
    const float* qkv_w    = (const float*)d_in[1];
    const float* qkv_s    = (const float*)d_in[2];
    const float* qkv_b    = (const float*)d_in[3];
    const float* pe_w     = (const float*)d_in[4];
    const float* pe_s     = (const float*)d_in[5];
    const float* pe_b     = (const float*)d_in[6];
    const float* proj_w   = (const float*)d_in[7];
    const float* proj_s   = (const float*)d_in[8];
    const float* proj_b   = (const float*)d_in[9];
    const float* pin_w    = (const float*)d_in[10];
    const float* dw_w     = (const float*)d_in[11];
    const float* fft_filt = (const float*)d_in[12];
    const float* pout_w   = (const float*)d_in[13];
    float* out = (float*)d_out;

    float* qkv   ; cudaGetSymbolAddress((void**)&qkv,    g_qkv);
    float* attn  ; cudaGetSymbolAddress((void**)&attn,   g_attn);
    float* attout; cudaGetSymbolAddress((void**)&attout, g_attout);
    float* xnew  ; cudaGetSymbolAddress((void**)&xnew,   g_xnew);
    float* pin   ; cudaGetSymbolAddress((void**)&pin,    g_pin);
    float* dwbuf ; cudaGetSymbolAddress((void**)&dwbuf,  g_dw);
    float* hid   ; cudaGetSymbolAddress((void**)&hid,    g_hid);
    float* yout  ; cudaGetSymbolAddress((void**)&yout,   g_yout);
    float* gtab  ; cudaGetSymbolAddress((void**)&gtab,   g_g);

    // 1. qkv = affine(conv1x1(x, qkv_w))
    gemm1x1_kernel<<<dim3(N_/64, CQKV/64, B_), 256>>>(x, qkv_w, qkv_s, qkv_b, nullptr, qkv, C_, CQKV, N_);
    // 2. S = Q^T K * scale
    attn_qk_kernel<<<dim3(N_/64, N_/64, B_*NH_), 256>>>(qkv, attn, 0.176776695296636893f);
    // 3. softmax rows
    softmax_kernel<<<B_*NH_*N_, 256>>>(attn);
    // 4. out = V @ S^T
    attn_pv_kernel<<<dim3(N_/64, 1, B_*NH_), 256>>>(qkv, attn, attout);
    // 5. attout += affine(dwconv3x3(v_img, pe_w))
    dwconv_kernel<<<(B_*C_*H_*W_ + 255)/256, 256>>>(qkv, pe_w, pe_s, pe_b, attout, C_, CQKV, 1, 1);
    // 6. xnew = x + affine(conv1x1(attout, proj_w))
    gemm1x1_kernel<<<dim3(N_/64, C_/64, B_), 256>>>(attout, proj_w, proj_s, proj_b, x, xnew, C_, C_, N_);
    // 7. pin = conv1x1(xnew, pin_w)
    gemm1x1_kernel<<<dim3(N_/64, C2/64, B_), 256>>>(xnew, pin_w, nullptr, nullptr, nullptr, pin, C_, C2, N_);
    // 8. dw = dwconv3x3(pin, dw_w)
    dwconv_kernel<<<(B_*C2*H_*W_ + 255)/256, 256>>>(pin, dw_w, nullptr, nullptr, dwbuf, C2, C2, 0, 0);
    // 9. hid = gelu(y1) * y2
    gate_kernel<<<(B_*HID*N_ + 255)/256, 256>>>(dwbuf, hid);
    // 10. yout = conv1x1(hid, pout_w)
    gemm1x1_kernel<<<dim3(N_/64, C_/64, B_), 256>>>(hid, pout_w, nullptr, nullptr, nullptr, yout, HID, C_, N_);
    // 11. circular-conv kernels from fft filter
    fft_g_kernel<<<C_, 64>>>(fft_filt, gtab);
    // 12. out = xnew + blockwise circconv(yout)
    fft_apply_kernel<<<B_*C_, 256>>>(yout, gtab, xnew, out);
}